// round 11
// baseline (speedup 1.0000x reference)
#include <cuda_runtime.h>

// Scratch (no allocations allowed): s = scaled B-projection, k = conv taps.
__device__ __align__(16) float g_s[4 * 16 * 64];      // [b][u][n]
__device__ __align__(16) float g_k[4 * 16 * 1024];    // [b][u][m]

#define TAPS 16
#define BQ 4
#define LQ 2048
#define DMQ 1024
#define NQ 64
#define CUTOFF (-30.0f)   // u*log_A below this => tap < e^-30 of signal

// ---------------------------------------------------------------------------
// K1: s[b,u,n] = (dot(x[b,u,:], W_B[n,:]) + b_B[n]) * exp(u*log_A[n])
// ONLY for active pairs (u*log_A[n] >= CUTOFF). Active set enumerated at
// runtime from log_A; slot -> (b,u,n) via CORRECT inclusive Hillis-Steele
// scan (R10 bug: scanned the raw cnt instead of the running sum).
// Entries outside the enumeration are never read (K2 uses the same bound).
// grid = 64 x 256 threads = 512 warp-slots for ~400 active dots.
// ---------------------------------------------------------------------------
__global__ void __launch_bounds__(256) s4_k1(const float* __restrict__ x,
                                             const float* __restrict__ W_B,
                                             const float* __restrict__ b_B,
                                             const float* __restrict__ log_A) {
    cudaTriggerProgrammaticLaunchCompletion();

    int w = threadIdx.x >> 5;
    int lane = threadIdx.x & 31;
    int u16 = lane & 15;

    // c_u for this lane's u (lanes 16..31 mirror 0..15)
    int cnt = 0;
    #pragma unroll
    for (int n = 0; n < NQ; n++) {
        float la = log_A[n];
        if ((float)u16 * la >= CUTOFF) cnt = n + 1;
    }
    // inclusive scan over the 16-lane pattern (upper half mirrors and only
    // reads upper-half lanes thanks to the (lane&15) >= off guard)
    int incl = cnt;
    #pragma unroll
    for (int off = 1; off < 16; off <<= 1) {
        int v = __shfl_up_sync(0xFFFFFFFFu, incl, off);   // running sum!
        if ((lane & 15) >= off) incl += v;
    }
    int pre = incl - cnt;                              // exclusive prefix
    int P = __shfl_sync(0xFFFFFFFFu, incl, 15);        // pairs per batch

    for (int slot = blockIdx.x * 8 + w; slot < BQ * P; slot += 512) {
        int b = slot / P;
        int r = slot - b * P;
        unsigned msk = __ballot_sync(0xFFFFFFFFu, (r >= pre) && (r < pre + cnt));
        int u = __ffs(msk) - 1;                        // lowest matching lane (<16)
        int n = r - __shfl_sync(0xFFFFFFFFu, pre, u);

        const float4* xr = reinterpret_cast<const float4*>(x + ((size_t)b * LQ + u) * DMQ);
        const float4* wr = reinterpret_cast<const float4*>(W_B + (size_t)n * DMQ);

        float4 xv[8], wv[8];
        #pragma unroll
        for (int j = 0; j < 8; j++) xv[j] = xr[lane + 32 * j];   // 16 independent
        #pragma unroll
        for (int j = 0; j < 8; j++) wv[j] = wr[lane + 32 * j];   // LDG.128

        float p0 = 0.0f, p1 = 0.0f;
        #pragma unroll
        for (int j = 0; j < 8; j++) {
            p0 += xv[j].x * wv[j].x + xv[j].y * wv[j].y;
            p1 += xv[j].z * wv[j].z + xv[j].w * wv[j].w;
        }
        float p = p0 + p1;
        #pragma unroll
        for (int off = 16; off; off >>= 1) p += __shfl_xor_sync(0xFFFFFFFFu, p, off);

        if (lane == 0)
            g_s[(b * TAPS + u) * NQ + n] = (p + b_B[n]) * expf((float)u * log_A[n]);
    }
}

// ---------------------------------------------------------------------------
// K2: k[b,u,m] = sum_{n < ncnt(u)} s[b,u,n] * C[n,m]
// ncnt(u) recomputed from log_A with the SAME cutoff as K1's enumeration,
// so unwritten g_s entries are never read. Sparsity = loop BOUND (no guards).
// grid = (16 m-tiles of 64, 16 (b, u-group of 4)), block = (64, 4).
// ---------------------------------------------------------------------------
__global__ void __launch_bounds__(256) s4_k2(const float* __restrict__ C,
                                             const float* __restrict__ log_A) {
    cudaTriggerProgrammaticLaunchCompletion();

    int b  = blockIdx.y >> 2;
    int ug = blockIdx.y & 3;
    int u  = ug * 4 + threadIdx.y;
    int bu = b * TAPS + u;
    int m  = blockIdx.x * 64 + threadIdx.x;

    int ncnt = 0;                                 // pre-sync (input only)
    #pragma unroll
    for (int n = 0; n < NQ; n++) {
        float la = log_A[n];
        if ((float)u * la >= CUTOFF) ncnt = n + 1;
    }

    cudaGridDependencySynchronize();              // wait for K1's g_s

    __shared__ float s[4][NQ];
    int tid = threadIdx.y * 64 + threadIdx.x;
    if (tid < 4 * NQ)
        s[tid >> 6][tid & 63] = g_s[(b * TAPS + ug * 4) * NQ + tid];
    __syncthreads();

    float acc = 0.0f;
    const float* sr = s[threadIdx.y];
    #pragma unroll 8
    for (int n = 0; n < ncnt; n++)
        acc += sr[n] * C[(size_t)n * DMQ + m];

    g_k[(size_t)bu * DMQ + m] = acc;
}

// ---------------------------------------------------------------------------
// K3: 16-tap per-channel causal FIR + D skip, packed f32x2 math.
// Rolling 16-slot window, t-tile = 32 (halo traffic 1.94x -> 1.47x).
// __launch_bounds__(256,3) -> 3 blocks/SM. grid = (2, 64, 4) = 512 blocks.
// ---------------------------------------------------------------------------
typedef unsigned long long u64t;

__device__ __forceinline__ u64t ffma2(u64t a, u64t b, u64t c) {
    u64t d;
    asm("fma.rn.f32x2 %0, %1, %2, %3;" : "=l"(d) : "l"(a), "l"(b), "l"(c));
    return d;
}
__device__ __forceinline__ u64t fmul2(u64t a, u64t b) {
    u64t d;
    asm("mul.rn.f32x2 %0, %1, %2;" : "=l"(d) : "l"(a), "l"(b));
    return d;
}

__global__ void __launch_bounds__(256, 3) s4_k3(const float* __restrict__ x,
                                                const float* __restrict__ D,
                                                float* __restrict__ out) {
    const int S = DMQ / 2;                       // row stride in pairs
    int c  = blockIdx.x * 256 + threadIdx.x;     // 0..511 channel pair
    int t0 = blockIdx.y * 32;
    int b  = blockIdx.z;

    const u64t* xp = reinterpret_cast<const u64t*>(x) + (size_t)b * LQ * S + c;
    u64t dp = reinterpret_cast<const u64t*>(D)[c];

    // Pre-sync: history x[t0-15 .. t0-1] into rolling slots 0..14
    u64t wbuf[16];
    #pragma unroll
    for (int i = 0; i < 15; i++) {
        int t = t0 - 15 + i;
        wbuf[i] = (t >= 0) ? xp[(size_t)t * S] : 0ull;   // 0x0 == {+0.f,+0.f}
    }

    cudaGridDependencySynchronize();             // wait for K2's g_k

    const u64t* kp = reinterpret_cast<const u64t*>(g_k) + (size_t)b * TAPS * S + c;
    u64t kr[TAPS];
    #pragma unroll
    for (int u = 0; u < TAPS; u++) kr[u] = kp[(size_t)u * S];

    u64t* op = reinterpret_cast<u64t*>(out) + (size_t)b * LQ * S + c;

    #pragma unroll
    for (int j = 0; j < 32; j++) {
        u64t xcur = xp[(size_t)(t0 + j) * S];
        wbuf[(15 + j) & 15] = xcur;              // overwrites t0+j-16 (dead)
        u64t a = fmul2(xcur, dp);                // D skip
        #pragma unroll
        for (int u = 0; u < TAPS; u++)
            a = ffma2(kr[u], wbuf[(15 + j - u) & 15], a);
        op[(size_t)(t0 + j) * S] = a;
    }
}

// ---------------------------------------------------------------------------
extern "C" void kernel_launch(void* const* d_in, const int* in_sizes, int n_in,
                              void* d_out, int out_size) {
    const float* x     = (const float*)d_in[0];   // (4, 2048, 1024)
    const float* W_B   = (const float*)d_in[1];   // (64, 1024)
    const float* b_B   = (const float*)d_in[2];   // (64,)
    const float* C     = (const float*)d_in[3];   // (64, 1024)
    const float* D     = (const float*)d_in[4];   // (1024,)
    const float* log_A = (const float*)d_in[5];   // (64,)
    float* out = (float*)d_out;

    s4_k1<<<64, 256>>>(x, W_B, b_B, log_A);

    cudaLaunchAttribute attr[1];
    attr[0].id = cudaLaunchAttributeProgrammaticStreamSerialization;
    attr[0].val.programmaticStreamSerializationAllowed = 1;

    // K2 (PDL secondary to K1; plain fallback)
    {
        cudaLaunchConfig_t cfg = {};
        cfg.gridDim  = dim3(16, 16);
        cfg.blockDim = dim3(64, 4);
        cfg.stream = 0;
        cfg.attrs = attr;
        cfg.numAttrs = 1;
        cudaError_t e = cudaLaunchKernelEx(&cfg, s4_k2, C, log_A);
        if (e != cudaSuccess) {
            (void)cudaGetLastError();
            s4_k2<<<dim3(16, 16), dim3(64, 4)>>>(C, log_A);
        }
    }

    // K3 (PDL secondary to K2; plain fallback)
    {
        cudaLaunchConfig_t cfg = {};
        cfg.gridDim  = dim3(2, 64, 4);
        cfg.blockDim = dim3(256, 1, 1);
        cfg.stream = 0;
        cfg.attrs = attr;
        cfg.numAttrs = 1;
        cudaError_t e = cudaLaunchKernelEx(&cfg, s4_k3, x, D, (float*)out);
        if (e != cudaSuccess) {
            (void)cudaGetLastError();
            s4_k3<<<dim3(2, 64, 4), 256>>>(x, D, out);
        }
    }
}